// round 1
// baseline (speedup 1.0000x reference)
#include <cuda_runtime.h>

// Problem constants: x [16,3,256,256] f32, thetas[12], phis[3] -> out [16,1,128,128] f32
#define B_   16
#define H2_  128
#define W2_  128
#define P_TOTAL (B_ * H2_ * W2_)   // 262144

// Gate constants (depend only on thetas/phis) computed once by prep kernel.
// g_cu[g] = {f1r, f1i, f2r, f2i} where f1 = -i e^{i t/2} = sin(t/2) - i cos(t/2)
//                                      f2 = -i e^{-i t/2} = -sin(t/2) - i cos(t/2)
// g_ph[l] = {cos(phi), sin(phi)}
__device__ float g_cu[12][4];
__device__ float g_ph[3][2];

__global__ void prep_kernel(const float* __restrict__ thetas,
                            const float* __restrict__ phis) {
    int t = threadIdx.x;
    if (t < 12) {
        float s, c;
        sincosf(0.5f * thetas[t], &s, &c);
        g_cu[t][0] = s;   g_cu[t][1] = -c;
        g_cu[t][2] = -s;  g_cu[t][3] = -c;
    }
    if (t < 3) {
        float s, c;
        sincosf(phis[t], &s, &c);
        g_ph[t][0] = c;   g_ph[t][1] = s;
    }
}

// State layout: amplitude index k = wire0*16 + wire1*8 + wire2*4 + wire3*2 + wire4
__global__ void __launch_bounds__(256)
sim_kernel(const float* __restrict__ x, float* __restrict__ out) {
    int p = blockIdx.x * 256 + threadIdx.x;
    if (p >= P_TOTAL) return;
    int b   = p >> 14;          // p / (128*128)
    int rem = p & 16383;
    int i   = rem >> 7;         // patch row
    int j   = rem & 127;        // patch col

    const float2* __restrict__ x2 = (const float2*)x;
    const float INV = 0.70710678118654752f;

    float sr[32], si[32];

    // ---------------- Layer 0 (special-cased: product state) ----------------
    {
        int rowbase = ((b * 3 + 0) * 256 + 2 * i) * 128 + j;
        float2 v0 = x2[rowbase];
        float2 v1 = x2[rowbase + 128];
        float ang[4] = {v0.x, v0.y, v1.x, v1.y};
        float cw[4], sw[4];
#pragma unroll
        for (int w = 0; w < 4; w++) __sincosf(0.5f * ang[w], &sw[w], &cw[w]);
        // product over wires 1..4: bit (8>>w)=0 -> cw[w], =1 -> (-i sw[w])
#pragma unroll
        for (int n = 0; n < 16; n++) {
            float re = INV, im = 0.f;
#pragma unroll
            for (int w = 0; w < 4; w++) {
                if (n & (8 >> w)) {
                    float t = re;
                    re = sw[w] * im;
                    im = -sw[w] * t;
                } else {
                    re *= cw[w];
                    im *= cw[w];
                }
            }
            sr[n]      = re; si[n]      = im;   // wire0 = 0
            sr[n + 16] = re; si[n + 16] = im;   // wire0 = 1 (same after H)
        }
    }

    // CU (ctrl, tgt) masks: (w1->w2),(w2->w3),(w3->w4),(w4->w1)
    const int cm[4] = {8, 4, 2, 1};
    const int tm[4] = {4, 2, 1, 8};

#pragma unroll
    for (int L = 0; L < 3; L++) {
        // -------- dense RX for layers 1,2 --------
        if (L > 0) {
            int rowbase = ((b * 3 + L) * 256 + 2 * i) * 128 + j;
            float2 v0 = x2[rowbase];
            float2 v1 = x2[rowbase + 128];
            float ang[4] = {v0.x, v0.y, v1.x, v1.y};
#pragma unroll
            for (int w = 0; w < 4; w++) {
                float s, c;
                __sincosf(0.5f * ang[w], &s, &c);
                int m = 8 >> w;
#pragma unroll
                for (int k = 0; k < 32; k++) {
                    if (!(k & m)) {
                        int k1 = k | m;
                        float a0r = sr[k],  a0i = si[k];
                        float a1r = sr[k1], a1i = si[k1];
                        sr[k]  =  c * a0r + s * a1i;
                        si[k]  =  c * a0i - s * a1r;
                        sr[k1] =  s * a0i + c * a1r;
                        si[k1] = -s * a0r + c * a1i;
                    }
                }
            }
        }
        // -------- controlled-U gates --------
#pragma unroll
        for (int w = 0; w < 4; w++) {
            int gi = 4 * L + w;
            float f1r = g_cu[gi][0], f1i = g_cu[gi][1];
            float f2r = g_cu[gi][2], f2i = g_cu[gi][3];
#pragma unroll
            for (int k = 0; k < 32; k++) {
                if ((k & cm[w]) && !(k & tm[w])) {
                    int k1 = k | tm[w];
                    float a0r = sr[k],  a0i = si[k];
                    float a1r = sr[k1], a1i = si[k1];
                    // new0 = f1 * old1 ; new1 = f2 * old0
                    sr[k]  = f1r * a1r - f1i * a1i;
                    si[k]  = f1r * a1i + f1i * a1r;
                    sr[k1] = f2r * a0r - f2i * a0i;
                    si[k1] = f2r * a0i + f2i * a0r;
                }
            }
        }
        // -------- CPhase on wires 0,1 (bits 16 & 8) --------
        {
            float pr = g_ph[L][0], pim = g_ph[L][1];
#pragma unroll
            for (int k = 0; k < 32; k++) {
                if ((k & 24) == 24) {
                    float ar = sr[k], ai = si[k];
                    sr[k] = pr * ar - pim * ai;
                    si[k] = pr * ai + pim * ar;
                }
            }
        }
    }

    // Final H on wire0 + <Z0>:  sum_k |.|^2*sign collapses to 2*Re(a0 conj(a1))
    float ev = 0.f;
#pragma unroll
    for (int k = 0; k < 16; k++)
        ev += 2.f * (sr[k] * sr[k + 16] + si[k] * si[k + 16]);

    out[p] = ev;
}

extern "C" void kernel_launch(void* const* d_in, const int* in_sizes, int n_in,
                              void* d_out, int out_size) {
    const float* x      = (const float*)d_in[0];
    const float* thetas = (const float*)d_in[1];
    const float* phis   = (const float*)d_in[2];
    float* out = (float*)d_out;

    prep_kernel<<<1, 32>>>(thetas, phis);
    sim_kernel<<<(P_TOTAL + 255) / 256, 256>>>(x, out);
}

// round 2
// speedup vs baseline: 1.1825x; 1.1825x over previous
#include <cuda_runtime.h>

typedef unsigned long long u64;

// x [16,3,256,256] f32, thetas[12], phis[3] -> out [16,1,128,128] f32
#define PPAIRS (16 * 128 * 64)   // 131072 threads, 2 patches each

__device__ float g_cu[12][4];
__device__ float g_ph[3][2];

__global__ void prep_kernel(const float* __restrict__ thetas,
                            const float* __restrict__ phis) {
    int t = threadIdx.x;
    if (t < 12) {
        float s, c;
        sincosf(0.5f * thetas[t], &s, &c);
        g_cu[t][0] = s;   g_cu[t][1] = -c;   // f1 = sin - i cos
        g_cu[t][2] = -s;  g_cu[t][3] = -c;   // f2 = -sin - i cos
    }
    if (t < 3) {
        float s, c;
        sincosf(phis[t], &s, &c);
        g_ph[t][0] = c;   g_ph[t][1] = s;
    }
}

// ---- packed f32x2 helpers ----
__device__ __forceinline__ u64 pk2(float lo, float hi) {
    u64 r; asm("mov.b64 %0,{%1,%2};" : "=l"(r) : "f"(lo), "f"(hi)); return r;
}
__device__ __forceinline__ u64 pk2b(float v) { return pk2(v, v); }
__device__ __forceinline__ void upk2(float& lo, float& hi, u64 v) {
    asm("mov.b64 {%0,%1},%2;" : "=f"(lo), "=f"(hi) : "l"(v));
}
__device__ __forceinline__ u64 fma2(u64 a, u64 b, u64 c) {
    u64 d; asm("fma.rn.f32x2 %0,%1,%2,%3;" : "=l"(d) : "l"(a), "l"(b), "l"(c)); return d;
}
__device__ __forceinline__ u64 mul2(u64 a, u64 b) {
    u64 d; asm("mul.rn.f32x2 %0,%1,%2;" : "=l"(d) : "l"(a), "l"(b)); return d;
}
__device__ __forceinline__ u64 neg2(u64 a) {
    const u64 SGN = 0x8000000080000000ULL;
    u64 d; asm("xor.b64 %0,%1,%2;" : "=l"(d) : "l"(a), "l"(SGN)); return d;
}

struct CS { u64 c, s; };
__device__ __forceinline__ CS cs2(float alo, float ahi) {
    float sl, cl, sh, ch;
    __sincosf(0.5f * alo, &sl, &cl);
    __sincosf(0.5f * ahi, &sh, &ch);
    CS r; r.c = pk2(cl, ch); r.s = pk2(sl, sh); return r;
}

// amplitude index (within 4 wires): bit8->w1 not used here; inside 16-amp space:
// n = w1*8 + w2*4 + w3*2 + w4. Full 32-amp: k = w0*16 + n.
__global__ void __launch_bounds__(128)
sim_kernel(const float* __restrict__ x, float* __restrict__ out) {
    int q   = blockIdx.x * 128 + threadIdx.x;
    int b   = q >> 13;        // 8192 pairs per image
    int rem = q & 8191;
    int i   = rem >> 6;       // patch row
    int jp  = rem & 63;       // column-pair

    const float4* __restrict__ x4 = (const float4*)x;

    u64 sr[32], si[32];

    // CU (ctrl,tgt) masks within 4-wire space
    const int cm[4] = {8, 4, 2, 1};
    const int tm[4] = {4, 2, 1, 8};

    // ================= Layer 0 =================
    {
        int base = ((b * 3 + 0) * 256 + 2 * i) * 64 + jp;
        float4 v0 = x4[base];
        float4 v1 = x4[base + 64];
        CS g0 = cs2(v0.x, v0.z), g1 = cs2(v0.y, v0.w);
        CS g2 = cs2(v1.x, v1.z), g3 = cs2(v1.y, v1.w);

        // product state: amp(n) = m(n) * (-i)^popc(n), m real, scaled by 1/sqrt2
        u64 INV2 = pk2b(0.70710678118654752f);
        u64 c0 = mul2(g0.c, INV2), s0 = mul2(g0.s, INV2);
        u64 ab[4] = { mul2(c0, g1.c), mul2(c0, g1.s), mul2(s0, g1.c), mul2(s0, g1.s) };
        u64 cd[4] = { mul2(g2.c, g3.c), mul2(g2.c, g3.s), mul2(g2.s, g3.c), mul2(g2.s, g3.s) };
#pragma unroll
        for (int n = 0; n < 16; n++) {
            u64 m = mul2(ab[n >> 2], cd[n & 3]);
            int pc = __popc(n) & 3;   // constant-folded
            if (pc == 0)      { sr[n] = m;        si[n] = 0ULL;     }
            else if (pc == 1) { sr[n] = 0ULL;     si[n] = neg2(m);  }
            else if (pc == 2) { sr[n] = neg2(m);  si[n] = 0ULL;     }
            else              { sr[n] = 0ULL;     si[n] = m;        }
        }
    }

    // Layer-0 CU gates on the 16-amp (wires 1-4) state: wire0 untouched yet
#pragma unroll
    for (int w = 0; w < 4; w++) {
        u64 f1r = pk2b(g_cu[w][0]), f1i = pk2b(g_cu[w][1]);
        u64 f2r = pk2b(g_cu[w][2]), f2i = pk2b(g_cu[w][3]);
        u64 nf1i = neg2(f1i), nf2i = neg2(f2i);
#pragma unroll
        for (int k = 0; k < 16; k++) {
            if ((k & cm[w]) && !(k & tm[w])) {
                int k1 = k | tm[w];
                u64 a0r = sr[k],  a0i = si[k];
                u64 a1r = sr[k1], a1i = si[k1];
                sr[k]  = fma2(nf1i, a1i, mul2(f1r, a1r));
                si[k]  = fma2(f1i,  a1r, mul2(f1r, a1i));
                sr[k1] = fma2(nf2i, a0i, mul2(f2r, a0r));
                si[k1] = fma2(f2i,  a0r, mul2(f2r, a0i));
            }
        }
    }

    // Split into wire0 branches at first CPhase: upper = lower (phased on w1=1)
    {
        u64 pr = pk2b(g_ph[0][0]), pi = pk2b(g_ph[0][1]);
        u64 npi = neg2(pi);
#pragma unroll
        for (int n = 0; n < 16; n++) {
            if (n & 8) {
                sr[16 + n] = fma2(npi, si[n], mul2(pr, sr[n]));
                si[16 + n] = fma2(pi,  sr[n], mul2(pr, si[n]));
            } else {
                sr[16 + n] = sr[n];
                si[16 + n] = si[n];
            }
        }
    }

    // ================= Layers 1, 2 =================
#pragma unroll
    for (int L = 1; L < 3; L++) {
        int base = ((b * 3 + L) * 256 + 2 * i) * 64 + jp;
        float4 v0 = x4[base];
        float4 v1 = x4[base + 64];
        CS g[4] = { cs2(v0.x, v0.z), cs2(v0.y, v0.w),
                    cs2(v1.x, v1.z), cs2(v1.y, v1.w) };
        // RX gates (dense, 32 amps)
#pragma unroll
        for (int w = 0; w < 4; w++) {
            u64 c = g[w].c, s = g[w].s, ns = neg2(s);
            int m = 8 >> w;
#pragma unroll
            for (int k = 0; k < 32; k++) {
                if (!(k & m)) {
                    int k1 = k | m;
                    u64 a0r = sr[k],  a0i = si[k];
                    u64 a1r = sr[k1], a1i = si[k1];
                    sr[k]  = fma2(s,  a1i, mul2(c,  a0r));
                    si[k]  = fma2(ns, a1r, mul2(c,  a0i));
                    sr[k1] = fma2(c,  a1r, mul2(s,  a0i));
                    si[k1] = fma2(c,  a1i, mul2(ns, a0r));
                }
            }
        }
        // CU gates (32 amps)
#pragma unroll
        for (int w = 0; w < 4; w++) {
            int gi = 4 * L + w;
            u64 f1r = pk2b(g_cu[gi][0]), f1i = pk2b(g_cu[gi][1]);
            u64 f2r = pk2b(g_cu[gi][2]), f2i = pk2b(g_cu[gi][3]);
            u64 nf1i = neg2(f1i), nf2i = neg2(f2i);
#pragma unroll
            for (int k = 0; k < 32; k++) {
                if ((k & cm[w]) && !(k & tm[w])) {
                    int k1 = k | tm[w];
                    u64 a0r = sr[k],  a0i = si[k];
                    u64 a1r = sr[k1], a1i = si[k1];
                    sr[k]  = fma2(nf1i, a1i, mul2(f1r, a1r));
                    si[k]  = fma2(f1i,  a1r, mul2(f1r, a1i));
                    sr[k1] = fma2(nf2i, a0i, mul2(f2r, a0r));
                    si[k1] = fma2(f2i,  a0r, mul2(f2r, a0i));
                }
            }
        }
        // CPhase on wires 0,1 (bits 16 & 8)
        {
            u64 pr = pk2b(g_ph[L][0]), pi = pk2b(g_ph[L][1]);
            u64 npi = neg2(pi);
#pragma unroll
            for (int k = 0; k < 32; k++) {
                if ((k & 24) == 24) {
                    u64 ar = sr[k], ai = si[k];
                    sr[k] = fma2(npi, ai, mul2(pr, ar));
                    si[k] = fma2(pi,  ar, mul2(pr, ai));
                }
            }
        }
    }

    // Final H on wire0 + <Z0> = 2*sum Re(a0k * conj(a1k))
    u64 acc = 0ULL;
#pragma unroll
    for (int k = 0; k < 16; k++) {
        acc = fma2(sr[k], sr[k + 16], acc);
        acc = fma2(si[k], si[k + 16], acc);
    }
    float lo, hi;
    upk2(lo, hi, acc);
    ((float2*)out)[q] = make_float2(2.f * lo, 2.f * hi);
}

extern "C" void kernel_launch(void* const* d_in, const int* in_sizes, int n_in,
                              void* d_out, int out_size) {
    const float* x      = (const float*)d_in[0];
    const float* thetas = (const float*)d_in[1];
    const float* phis   = (const float*)d_in[2];
    float* out = (float*)d_out;

    prep_kernel<<<1, 32>>>(thetas, phis);
    sim_kernel<<<PPAIRS / 128, 128>>>(x, out);
}